// round 3
// baseline (speedup 1.0000x reference)
#include <cuda_runtime.h>
#include <stdint.h>

#define Dd 128
#define Ll 200
#define Bb 4096
#define NITEMS 100000

// Scratch (static device globals: allocation-free per harness rules)
__device__ float g_KW[(NITEMS + 1) * Dd];   // item_emb @ Wk, 51.2 MB
__device__ float g_klp[Bb];
__device__ int   g_cnt[Bb];

// ---------------------------------------------------------------- utilities

__device__ __forceinline__ uint32_t rotl32(uint32_t x, int d) {
    return (x << d) | (x >> (32 - d));
}

// Exact JAX threefry2x32 (20 rounds)
__device__ __forceinline__ void threefry2x32(uint32_t k0, uint32_t k1,
                                             uint32_t c0, uint32_t c1,
                                             uint32_t& o0, uint32_t& o1) {
    uint32_t ks2 = k0 ^ k1 ^ 0x1BD11BDAu;
    uint32_t x0 = c0 + k0, x1 = c1 + k1;
#define TF_R(r) { x0 += x1; x1 = rotl32(x1, r); x1 ^= x0; }
    TF_R(13) TF_R(15) TF_R(26) TF_R(6)  x0 += k1;  x1 += ks2 + 1u;
    TF_R(17) TF_R(29) TF_R(16) TF_R(24) x0 += ks2; x1 += k0 + 2u;
    TF_R(13) TF_R(15) TF_R(26) TF_R(6)  x0 += k0;  x1 += k1 + 3u;
    TF_R(17) TF_R(29) TF_R(16) TF_R(24) x0 += k1;  x1 += ks2 + 4u;
    TF_R(13) TF_R(15) TF_R(26) TF_R(6)  x0 += ks2; x1 += k0 + 5u;
#undef TF_R
    o0 = x0; o1 = x1;
}

// jax.random.normal(key=(0,k1), shape)[flat idx] under
// jax_threefry_partitionable=True (default in modern JAX):
//   counter = 64-bit flat index -> (c0 = hi32 = 0, c1 = lo32 = idx)
//   32-bit draw = out0 ^ out1
__device__ __forceinline__ float jax_normal(uint32_t k1, uint32_t idx) {
    uint32_t o0, o1;
    threefry2x32(0u, k1, 0u, idx, o0, o1);
    uint32_t bits = o0 ^ o1;
    float f = __uint_as_float((bits >> 9) | 0x3F800000u) - 1.0f;  // [0,1)
    const float LO = -0.99999994f;                                // nextafter(-1,0)
    float u = fmaf(f, 2.0f, LO);                                  // (hi-lo) rounds to 2.0f
    u = fmaxf(u, LO);
    return 1.41421356f * erfinvf(u);
}

// tanh via MUFU ex2 + rcp (accurate to ~1e-6, 2 MUFU ops instead of slow sw poly)
__device__ __forceinline__ float fast_tanh(float x) {
    float e;
    asm("ex2.approx.f32 %0, %1;" : "=f"(e) : "f"(x * 2.8853900817779268f)); // 2*log2(e)
    float r;
    asm("rcp.approx.f32 %0, %1;" : "=f"(r) : "f"(e + 1.0f));
    return fmaf(-2.0f, r, 1.0f);    // 1 - 2/(e^{2x}+1)
}

__device__ __forceinline__ float breduce_sum(float v, volatile float* red) {
    int tid = threadIdx.x, lane = tid & 31, wrp = tid >> 5;
#pragma unroll
    for (int o = 16; o; o >>= 1) v += __shfl_down_sync(0xffffffffu, v, o);
    if (lane == 0) red[wrp] = v;
    __syncthreads();
    float r = (red[0] + red[1]) + (red[2] + red[3]);
    __syncthreads();
    return r;
}

__device__ __forceinline__ float breduce_max(float v, volatile float* red) {
    int tid = threadIdx.x, lane = tid & 31, wrp = tid >> 5;
#pragma unroll
    for (int o = 16; o; o >>= 1) v = fmaxf(v, __shfl_down_sync(0xffffffffu, v, o));
    if (lane == 0) red[wrp] = v;
    __syncthreads();
    float r = fmaxf(fmaxf(red[0], red[1]), fmaxf(red[2], red[3]));
    __syncthreads();
    return r;
}

// ------------------------------------------- Kernel A: KW = item_emb @ Wk
// 64 rows per block, 256 threads, thread computes 8 rows x 4 cols.
__global__ __launch_bounds__(256) void kw_kernel(const float* __restrict__ item_emb,
                                                 const float* __restrict__ Wk) {
    __shared__ __align__(16) float sA[64 * 128];
    const int t = threadIdx.x;
    const int row0 = blockIdx.x * 64;

    for (int i = t; i < 64 * 32; i += 256) {
        int r = i >> 5, c = i & 31;
        float4 val = make_float4(0.f, 0.f, 0.f, 0.f);
        if (row0 + r <= NITEMS)
            val = ((const float4*)(item_emb + (size_t)(row0 + r) * Dd))[c];
        ((float4*)sA)[i] = val;
    }
    __syncthreads();

    const int cg = t & 31;   // cols 4*cg .. 4*cg+3
    const int rg = t >> 5;   // rows rg*8 .. rg*8+7
    float acc[8][4];
#pragma unroll
    for (int i = 0; i < 8; i++)
#pragma unroll
        for (int j = 0; j < 4; j++) acc[i][j] = 0.f;

    const float* Arow = sA + rg * 8 * 128;
#pragma unroll 4
    for (int e = 0; e < 128; e++) {
        float4 w4 = ((const float4*)(Wk + e * Dd))[cg];
#pragma unroll
        for (int i = 0; i < 8; i++) {
            float a = Arow[i * 128 + e];
            acc[i][0] = fmaf(a, w4.x, acc[i][0]);
            acc[i][1] = fmaf(a, w4.y, acc[i][1]);
            acc[i][2] = fmaf(a, w4.z, acc[i][2]);
            acc[i][3] = fmaf(a, w4.w, acc[i][3]);
        }
    }
#pragma unroll
    for (int i = 0; i < 8; i++) {
        int r = row0 + rg * 8 + i;
        if (r <= NITEMS)
            *(float4*)(g_KW + (size_t)r * Dd + cg * 4) =
                make_float4(acc[i][0], acc[i][1], acc[i][2], acc[i][3]);
    }
}

// ------------------------------------------- Kernel C: fused BAM forward
__global__ __launch_bounds__(128) void fused_kernel(
    const float* __restrict__ user_emb,
    const float* __restrict__ item_emb,
    const float* __restrict__ Wq,
    const float* __restrict__ b_att,
    const float* __restrict__ v_att,
    const float* __restrict__ ln_u_g, const float* __restrict__ ln_u_b,
    const float* __restrict__ ln_i_g, const float* __restrict__ ln_i_b,
    const float* __restrict__ pred_W, const float* __restrict__ pred_b,
    const int* __restrict__ user_hist,
    const int* __restrict__ user_idx,
    const int* __restrict__ item_idx,
    float* __restrict__ out)
{
    __shared__ __align__(16) float sh_q[Dd];
    __shared__ __align__(16) float sh_u[Dd];
    __shared__ __align__(16) float sh_v[Dd];
    __shared__ int   sh_r[Ll];
    __shared__ float sh_s[Ll];
    __shared__ float sh_w1[Ll];
    __shared__ float sh_w2[Ll];
    __shared__ float red[4];

    const int tid  = threadIdx.x;
    const int lane = tid & 31;
    const int wrp  = tid >> 5;
    const int b    = blockIdx.x;
    const int uidx = user_idx[b];
    const int tgt  = item_idx[b];

    sh_u[tid] = user_emb[(size_t)uidx * Dd + tid];
    sh_v[tid] = v_att[tid];
    float validf = 0.f;
    for (int l = tid; l < Ll; l += 128) {
        int r = user_hist[(size_t)uidx * Ll + l];
        bool ok = (r != tgt) && (r != NITEMS);
        sh_r[l] = ok ? r : -1;
        validf += ok ? 1.f : 0.f;
    }
    __syncthreads();

    // qq = user_row @ Wq + b_att  (thread owns output column tid)
    float acc = b_att[tid];
#pragma unroll 8
    for (int e = 0; e < Dd; e++)
        acc = fmaf(sh_u[e], Wq[e * Dd + tid], acc);
    sh_q[tid] = acc;

    float nvf = breduce_sum(validf, red);   // also syncs sh_q
    int n_valid = (int)(nvf + 0.5f);
    float nv_clamped = (n_valid > 0) ? (float)n_valid : 1.0f;
    float mu_p = -logf(nv_clamped);

    // scores: warp per l, lane covers 4 dims
    for (int l = wrp; l < Ll; l += 4) {
        int r = sh_r[l];
        float sval = -1e30f;
        if (r >= 0) {
            float4 kw = *(const float4*)(g_KW + (size_t)r * Dd + lane * 4);
            float4 q4 = *(const float4*)(sh_q + lane * 4);
            float4 v4 = *(const float4*)(sh_v + lane * 4);
            float t = v4.x * fast_tanh(q4.x + kw.x);
            t = fmaf(v4.y, fast_tanh(q4.y + kw.y), t);
            t = fmaf(v4.z, fast_tanh(q4.z + kw.z), t);
            t = fmaf(v4.w, fast_tanh(q4.w + kw.w), t);
#pragma unroll
            for (int o = 16; o; o >>= 1) t += __shfl_down_sync(0xffffffffu, t, o);
            sval = t * 0.25f;   // / TAU
        }
        if (lane == 0) sh_s[l] = sval;
    }
    __syncthreads();

    // softmax
    float m = -1e30f;
    for (int l = tid; l < Ll; l += 128) m = fmaxf(m, sh_s[l]);
    m = breduce_max(m, red);

    float esum = 0.f;
    for (int l = tid; l < Ll; l += 128) {
        float e = 0.f;
        if (sh_r[l] >= 0) e = expf(sh_s[l] - m);
        sh_s[l] = e;
        esum += e;
    }
    esum = breduce_sum(esum, red);
    float inv_es = (esum > 0.f) ? (1.0f / esum) : 0.f;

    // lognormal sampling (exact JAX partitionable threefry) + KL
    float klacc = 0.f;
    for (int l = tid; l < Ll; l += 128) {
        float w1 = 0.f, w2 = 0.f;
        if (sh_r[l] >= 0) {
            float alpha = sh_s[l] * inv_es;
            float mu = logf(alpha + 1e-24f);
            uint32_t idx = (uint32_t)(b * Ll + l);
            float e1 = jax_normal(1u, idx);
            float e2 = jax_normal(2u, idx);
            w1 = expf(fmaf(0.1f, e1, mu));
            w2 = expf(fmaf(0.1f, e2, mu));
            float dmu = mu - mu_p;
            klacc += 1.8075851f + 0.5f * dmu * dmu;  // log(10)-0.5+SIG_Q^2/2 + d^2/2
        }
        sh_w1[l] = w1;
        sh_w2[l] = w2;
    }
    float klsum = breduce_sum(klacc, red);
    if (tid == 0) { g_klp[b] = klsum; g_cnt[b] = n_valid; }

    float s1 = 0.f, s2 = 0.f;
    for (int l = tid; l < Ll; l += 128) { s1 += sh_w1[l]; s2 += sh_w2[l]; }
    float S1 = breduce_sum(s1, red);
    float S2 = breduce_sum(s2, red);
    float i1 = 1.0f / (S1 + 1e-12f);
    float i2 = 1.0f / (S2 + 1e-12f);

    // contexts (single gather of each item row serves both draws)
    float cu = 0.f, ci = 0.f;
#pragma unroll 4
    for (int l = 0; l < Ll; l++) {
        int r = sh_r[l];
        if (r >= 0) {
            float vv = item_emb[(size_t)r * Dd + tid];
            cu = fmaf(sh_w1[l], vv, cu);
            ci = fmaf(sh_w2[l], vv, ci);
        }
    }
    cu *= i1; ci *= i2;

    // layernorm(u ctx * user_emb)
    float xu = cu * sh_u[tid];
    float mean_u = breduce_sum(xu, red) * (1.0f / Dd);
    float du = xu - mean_u;
    float var_u = breduce_sum(du * du, red) * (1.0f / Dd);
    float us = du * rsqrtf(var_u + 1e-5f) * ln_u_g[tid] + ln_u_b[tid];

    // layernorm(i ctx * item_emb[target])
    float xi = ci * item_emb[(size_t)tgt * Dd + tid];
    float mean_i = breduce_sum(xi, red) * (1.0f / Dd);
    float di = xi - mean_i;
    float var_i = breduce_sum(di * di, red) * (1.0f / Dd);
    float is_ = di * rsqrtf(var_i + 1e-5f) * ln_i_g[tid] + ln_i_b[tid];

    float pv = us * is_ * pred_W[tid];
    float dot = breduce_sum(pv, red);
    if (tid == 0) out[b] = dot + pred_b[0];
}

// ------------------------------------------- Kernel D: deterministic KL reduce
__global__ __launch_bounds__(256) void kl_reduce_kernel(float* __restrict__ out,
                                                        int out_size) {
    __shared__ float rs[8];
    __shared__ int   ri[8];
    int tid = threadIdx.x;
    float s = 0.f; int c = 0;
    for (int i = tid; i < Bb; i += 256) { s += g_klp[i]; c += g_cnt[i]; }
#pragma unroll
    for (int o = 16; o; o >>= 1) {
        s += __shfl_down_sync(0xffffffffu, s, o);
        c += __shfl_down_sync(0xffffffffu, c, o);
    }
    if ((tid & 31) == 0) { rs[tid >> 5] = s; ri[tid >> 5] = c; }
    __syncthreads();
    if (tid == 0) {
        float S = 0.f; int C = 0;
        for (int i = 0; i < 8; i++) { S += rs[i]; C += ri[i]; }
        if (C < 1) C = 1;
        float kl = 0.25f * S / (float)C;   // BETA * sum / cnt ; (kl_u+kl_i)/2 == kl_u
        if (out_size > Bb) out[Bb] = kl;
    }
}

// ------------------------------------------- launcher
extern "C" void kernel_launch(void* const* d_in, const int* in_sizes, int n_in,
                              void* d_out, int out_size) {
    const float* user_emb = (const float*)d_in[0];
    const float* item_emb = (const float*)d_in[1];
    const float* Wq       = (const float*)d_in[2];
    const float* Wk       = (const float*)d_in[3];
    const float* b_att    = (const float*)d_in[4];
    const float* v_att    = (const float*)d_in[5];
    const float* ln_u_g   = (const float*)d_in[6];
    const float* ln_u_b   = (const float*)d_in[7];
    const float* ln_i_g   = (const float*)d_in[8];
    const float* ln_i_b   = (const float*)d_in[9];
    const float* pred_W   = (const float*)d_in[10];
    const float* pred_b   = (const float*)d_in[11];
    const int* user_hist  = (const int*)d_in[12];
    const int* user_idx   = (const int*)d_in[13];
    const int* item_idx   = (const int*)d_in[14];
    float* out = (float*)d_out;

    kw_kernel<<<(NITEMS + 1 + 63) / 64, 256>>>(item_emb, Wk);
    fused_kernel<<<Bb, 128>>>(user_emb, item_emb, Wq, b_att, v_att,
                              ln_u_g, ln_u_b, ln_i_g, ln_i_b,
                              pred_W, pred_b, user_hist, user_idx, item_idx, out);
    kl_reduce_kernel<<<1, 256>>>(out, out_size);
}

// round 4
// speedup vs baseline: 1.3082x; 1.3082x over previous
#include <cuda_runtime.h>
#include <stdint.h>

#define Dd 128
#define Ll 200
#define Bb 4096
#define NITEMS 100000

// Scratch (static device globals: allocation-free per harness rules)
__device__ float g_KW[(NITEMS + 1) * Dd];   // item_emb @ Wk, 51.2 MB
__device__ float g_klp[Bb];
__device__ int   g_cnt[Bb];

// ---------------------------------------------------------------- utilities

__device__ __forceinline__ uint32_t rotl32(uint32_t x, int d) {
    return (x << d) | (x >> (32 - d));
}

// Exact JAX threefry2x32 (20 rounds)
__device__ __forceinline__ void threefry2x32(uint32_t k0, uint32_t k1,
                                             uint32_t c0, uint32_t c1,
                                             uint32_t& o0, uint32_t& o1) {
    uint32_t ks2 = k0 ^ k1 ^ 0x1BD11BDAu;
    uint32_t x0 = c0 + k0, x1 = c1 + k1;
#define TF_R(r) { x0 += x1; x1 = rotl32(x1, r); x1 ^= x0; }
    TF_R(13) TF_R(15) TF_R(26) TF_R(6)  x0 += k1;  x1 += ks2 + 1u;
    TF_R(17) TF_R(29) TF_R(16) TF_R(24) x0 += ks2; x1 += k0 + 2u;
    TF_R(13) TF_R(15) TF_R(26) TF_R(6)  x0 += k0;  x1 += k1 + 3u;
    TF_R(17) TF_R(29) TF_R(16) TF_R(24) x0 += k1;  x1 += ks2 + 4u;
    TF_R(13) TF_R(15) TF_R(26) TF_R(6)  x0 += ks2; x1 += k0 + 5u;
#undef TF_R
    o0 = x0; o1 = x1;
}

// jax.random.normal under jax_threefry_partitionable=True:
//   counter = 64-bit flat index -> (c0 = 0, c1 = idx); 32-bit draw = o0 ^ o1
__device__ __forceinline__ float jax_normal(uint32_t k1, uint32_t idx) {
    uint32_t o0, o1;
    threefry2x32(0u, k1, 0u, idx, o0, o1);
    uint32_t bits = o0 ^ o1;
    float f = __uint_as_float((bits >> 9) | 0x3F800000u) - 1.0f;  // [0,1)
    const float LO = -0.99999994f;                                // nextafter(-1,0)
    float u = fmaf(f, 2.0f, LO);
    u = fmaxf(u, LO);
    return 1.41421356f * erfinvf(u);
}

// Single-MUFU tanh (sm_75+ tanh.approx)
__device__ __forceinline__ float fast_tanh(float x) {
    float y;
    asm("tanh.approx.f32 %0, %1;" : "=f"(y) : "f"(x));
    return y;
}

__device__ __forceinline__ uint32_t f2tf32(float x) {
    uint32_t o;
    asm("cvt.rna.tf32.f32 %0, %1;" : "=r"(o) : "f"(x));
    return o;
}

__device__ __forceinline__ float breduce_sum(float v, volatile float* red) {
    int tid = threadIdx.x, lane = tid & 31, wrp = tid >> 5;
#pragma unroll
    for (int o = 16; o; o >>= 1) v += __shfl_down_sync(0xffffffffu, v, o);
    if (lane == 0) red[wrp] = v;
    __syncthreads();
    float r = (red[0] + red[1]) + (red[2] + red[3]);
    __syncthreads();
    return r;
}

__device__ __forceinline__ float breduce_max(float v, volatile float* red) {
    int tid = threadIdx.x, lane = tid & 31, wrp = tid >> 5;
#pragma unroll
    for (int o = 16; o; o >>= 1) v = fmaxf(v, __shfl_down_sync(0xffffffffu, v, o));
    if (lane == 0) red[wrp] = v;
    __syncthreads();
    float r = fmaxf(fmaxf(red[0], red[1]), fmaxf(red[2], red[3]));
    __syncthreads();
    return r;
}

// ------------------------------------------- Kernel A: KW = item_emb @ Wk
// tf32 tensor-core GEMM. Persistent blocks; Wk^T resident in shared (tf32,
// padded 132 floats/row for conflict-free LDS). 64-row A tiles.
// Block = 128 threads (4 warps); warp covers 32 rows x 64 cols
//   (2 m16 frags x 8 n8 tiles), k-loop 16 steps of k=8.
#define KW_NBLK 296
#define KW_TILES ((NITEMS + 1 + 63) / 64)   // 1563
#define PADW 132

__global__ __launch_bounds__(128) void kw_kernel(const float* __restrict__ item_emb,
                                                 const float* __restrict__ Wk) {
    extern __shared__ uint32_t smem_u[];
    uint32_t* sA = smem_u;                 // [64][132] tf32
    uint32_t* sW = smem_u + 64 * PADW;     // [128 n][132] tf32 (transposed Wk)

    const int tid  = threadIdx.x;
    const int lane = tid & 31;
    const int wid  = tid >> 5;
    const int gid  = lane >> 2;      // 0..7
    const int tig  = lane & 3;       // 0..3
    const int stripe  = (wid & 1) * 32;
    const int colhalf = (wid >> 1) * 64;

    // Load Wk transposed into shared (once per block)
    for (int i = tid; i < 128 * 128; i += 128) {
        int k = i >> 7, n = i & 127;
        sW[n * PADW + k] = f2tf32(Wk[k * Dd + n]);
    }
    __syncthreads();

    for (int t = blockIdx.x; t < KW_TILES; t += KW_NBLK) {
        const int row0 = t * 64;

        // fill A tile (tf32-converted)
        for (int i = tid; i < 64 * 32; i += 128) {
            int r = i >> 5, c4 = i & 31;
            float4 v = make_float4(0.f, 0.f, 0.f, 0.f);
            if (row0 + r <= NITEMS)
                v = ((const float4*)(item_emb + (size_t)(row0 + r) * Dd))[c4];
            uint4 w;
            w.x = f2tf32(v.x); w.y = f2tf32(v.y);
            w.z = f2tf32(v.z); w.w = f2tf32(v.w);
            *(uint4*)(sA + r * PADW + c4 * 4) = w;
        }
        __syncthreads();

        float acc[2][8][4];
#pragma unroll
        for (int mi = 0; mi < 2; mi++)
#pragma unroll
            for (int ni = 0; ni < 8; ni++)
#pragma unroll
                for (int j = 0; j < 4; j++) acc[mi][ni][j] = 0.f;

#pragma unroll
        for (int ks = 0; ks < 16; ks++) {
            const int k0 = ks * 8;
            uint32_t a[2][4];
#pragma unroll
            for (int mi = 0; mi < 2; mi++) {
                int r = stripe + mi * 16 + gid;
                a[mi][0] = sA[r * PADW + k0 + tig];
                a[mi][1] = sA[(r + 8) * PADW + k0 + tig];
                a[mi][2] = sA[r * PADW + k0 + tig + 4];
                a[mi][3] = sA[(r + 8) * PADW + k0 + tig + 4];
            }
            uint32_t bfr[8][2];
#pragma unroll
            for (int ni = 0; ni < 8; ni++) {
                int n = colhalf + ni * 8 + gid;
                bfr[ni][0] = sW[n * PADW + k0 + tig];
                bfr[ni][1] = sW[n * PADW + k0 + tig + 4];
            }
#pragma unroll
            for (int mi = 0; mi < 2; mi++)
#pragma unroll
                for (int ni = 0; ni < 8; ni++) {
                    asm volatile(
                        "mma.sync.aligned.m16n8k8.row.col.f32.tf32.tf32.f32 "
                        "{%0,%1,%2,%3}, {%4,%5,%6,%7}, {%8,%9}, {%0,%1,%2,%3};"
                        : "+f"(acc[mi][ni][0]), "+f"(acc[mi][ni][1]),
                          "+f"(acc[mi][ni][2]), "+f"(acc[mi][ni][3])
                        : "r"(a[mi][0]), "r"(a[mi][1]), "r"(a[mi][2]), "r"(a[mi][3]),
                          "r"(bfr[ni][0]), "r"(bfr[ni][1]));
                }
        }

        // epilogue: write C directly from regs
#pragma unroll
        for (int mi = 0; mi < 2; mi++) {
            int r0 = row0 + stripe + mi * 16 + gid;
            int r1 = r0 + 8;
#pragma unroll
            for (int ni = 0; ni < 8; ni++) {
                int c = colhalf + ni * 8 + tig * 2;
                if (r0 <= NITEMS)
                    *(float2*)(g_KW + (size_t)r0 * Dd + c) =
                        make_float2(acc[mi][ni][0], acc[mi][ni][1]);
                if (r1 <= NITEMS)
                    *(float2*)(g_KW + (size_t)r1 * Dd + c) =
                        make_float2(acc[mi][ni][2], acc[mi][ni][3]);
            }
        }
        __syncthreads();   // protect sA before next tile refill
    }
}

// ------------------------------------------- Kernel C: fused BAM forward
__global__ __launch_bounds__(128) void fused_kernel(
    const float* __restrict__ user_emb,
    const float* __restrict__ item_emb,
    const float* __restrict__ Wq,
    const float* __restrict__ b_att,
    const float* __restrict__ v_att,
    const float* __restrict__ ln_u_g, const float* __restrict__ ln_u_b,
    const float* __restrict__ ln_i_g, const float* __restrict__ ln_i_b,
    const float* __restrict__ pred_W, const float* __restrict__ pred_b,
    const int* __restrict__ user_hist,
    const int* __restrict__ user_idx,
    const int* __restrict__ item_idx,
    float* __restrict__ out)
{
    __shared__ __align__(16) float sh_q[Dd];
    __shared__ __align__(16) float sh_u[Dd];
    __shared__ __align__(16) float sh_v[Dd];
    __shared__ int   sh_r[Ll];
    __shared__ float sh_s[Ll];
    __shared__ float sh_w1[Ll];
    __shared__ float sh_w2[Ll];
    __shared__ float red[4];

    const int tid  = threadIdx.x;
    const int lane = tid & 31;
    const int wrp  = tid >> 5;
    const int b    = blockIdx.x;
    const int uidx = user_idx[b];
    const int tgt  = item_idx[b];

    sh_u[tid] = user_emb[(size_t)uidx * Dd + tid];
    sh_v[tid] = v_att[tid];
    float validf = 0.f;
    for (int l = tid; l < Ll; l += 128) {
        int r = user_hist[(size_t)uidx * Ll + l];
        bool ok = (r != tgt) && (r != NITEMS);
        sh_r[l] = ok ? r : -1;
        validf += ok ? 1.f : 0.f;
    }
    __syncthreads();

    // qq = user_row @ Wq + b_att  (thread owns output column tid)
    float acc = b_att[tid];
#pragma unroll 8
    for (int e = 0; e < Dd; e++)
        acc = fmaf(sh_u[e], Wq[e * Dd + tid], acc);
    sh_q[tid] = acc;

    float nvf = breduce_sum(validf, red);   // also syncs sh_q
    int n_valid = (int)(nvf + 0.5f);
    float nv_clamped = (n_valid > 0) ? (float)n_valid : 1.0f;
    float mu_p = -logf(nv_clamped);

    // scores: warp per l, lane covers 4 dims
    for (int l = wrp; l < Ll; l += 4) {
        int r = sh_r[l];
        float sval = -1e30f;
        if (r >= 0) {
            float4 kw = *(const float4*)(g_KW + (size_t)r * Dd + lane * 4);
            float4 q4 = *(const float4*)(sh_q + lane * 4);
            float4 v4 = *(const float4*)(sh_v + lane * 4);
            float t = v4.x * fast_tanh(q4.x + kw.x);
            t = fmaf(v4.y, fast_tanh(q4.y + kw.y), t);
            t = fmaf(v4.z, fast_tanh(q4.z + kw.z), t);
            t = fmaf(v4.w, fast_tanh(q4.w + kw.w), t);
#pragma unroll
            for (int o = 16; o; o >>= 1) t += __shfl_down_sync(0xffffffffu, t, o);
            sval = t * 0.25f;   // / TAU
        }
        if (lane == 0) sh_s[l] = sval;
    }
    __syncthreads();

    // softmax
    float m = -1e30f;
    for (int l = tid; l < Ll; l += 128) m = fmaxf(m, sh_s[l]);
    m = breduce_max(m, red);

    float esum = 0.f;
    for (int l = tid; l < Ll; l += 128) {
        float e = 0.f;
        if (sh_r[l] >= 0) e = expf(sh_s[l] - m);
        sh_s[l] = e;
        esum += e;
    }
    esum = breduce_sum(esum, red);
    float inv_es = (esum > 0.f) ? (1.0f / esum) : 0.f;

    // lognormal sampling (exact JAX partitionable threefry) + KL
    float klacc = 0.f;
    for (int l = tid; l < Ll; l += 128) {
        float w1 = 0.f, w2 = 0.f;
        if (sh_r[l] >= 0) {
            float alpha = sh_s[l] * inv_es;
            float mu = logf(alpha + 1e-24f);
            uint32_t idx = (uint32_t)(b * Ll + l);
            float e1 = jax_normal(1u, idx);
            float e2 = jax_normal(2u, idx);
            w1 = expf(fmaf(0.1f, e1, mu));
            w2 = expf(fmaf(0.1f, e2, mu));
            float dmu = mu - mu_p;
            klacc += 1.8075851f + 0.5f * dmu * dmu;  // log(10)-0.5+SIG_Q^2/2 + d^2/2
        }
        sh_w1[l] = w1;
        sh_w2[l] = w2;
    }
    float klsum = breduce_sum(klacc, red);
    if (tid == 0) { g_klp[b] = klsum; g_cnt[b] = n_valid; }

    float s1 = 0.f, s2 = 0.f;
    for (int l = tid; l < Ll; l += 128) { s1 += sh_w1[l]; s2 += sh_w2[l]; }
    float S1 = breduce_sum(s1, red);
    float S2 = breduce_sum(s2, red);
    float i1 = 1.0f / (S1 + 1e-12f);
    float i2 = 1.0f / (S2 + 1e-12f);

    // contexts (single gather of each item row serves both draws)
    float cu = 0.f, ci = 0.f;
#pragma unroll 4
    for (int l = 0; l < Ll; l++) {
        int r = sh_r[l];
        if (r >= 0) {
            float vv = item_emb[(size_t)r * Dd + tid];
            cu = fmaf(sh_w1[l], vv, cu);
            ci = fmaf(sh_w2[l], vv, ci);
        }
    }
    cu *= i1; ci *= i2;

    // layernorm(u ctx * user_emb)
    float xu = cu * sh_u[tid];
    float mean_u = breduce_sum(xu, red) * (1.0f / Dd);
    float du = xu - mean_u;
    float var_u = breduce_sum(du * du, red) * (1.0f / Dd);
    float us = du * rsqrtf(var_u + 1e-5f) * ln_u_g[tid] + ln_u_b[tid];

    // layernorm(i ctx * item_emb[target])
    float xi = ci * item_emb[(size_t)tgt * Dd + tid];
    float mean_i = breduce_sum(xi, red) * (1.0f / Dd);
    float di = xi - mean_i;
    float var_i = breduce_sum(di * di, red) * (1.0f / Dd);
    float is_ = di * rsqrtf(var_i + 1e-5f) * ln_i_g[tid] + ln_i_b[tid];

    float pv = us * is_ * pred_W[tid];
    float dot = breduce_sum(pv, red);
    if (tid == 0) out[b] = dot + pred_b[0];
}

// ------------------------------------------- Kernel D: deterministic KL reduce
__global__ __launch_bounds__(256) void kl_reduce_kernel(float* __restrict__ out,
                                                        int out_size) {
    __shared__ float rs[8];
    __shared__ int   ri[8];
    int tid = threadIdx.x;
    float s = 0.f; int c = 0;
    for (int i = tid; i < Bb; i += 256) { s += g_klp[i]; c += g_cnt[i]; }
#pragma unroll
    for (int o = 16; o; o >>= 1) {
        s += __shfl_down_sync(0xffffffffu, s, o);
        c += __shfl_down_sync(0xffffffffu, c, o);
    }
    if ((tid & 31) == 0) { rs[tid >> 5] = s; ri[tid >> 5] = c; }
    __syncthreads();
    if (tid == 0) {
        float S = 0.f; int C = 0;
        for (int i = 0; i < 8; i++) { S += rs[i]; C += ri[i]; }
        if (C < 1) C = 1;
        float kl = 0.25f * S / (float)C;   // BETA * sum / cnt ; (kl_u+kl_i)/2 == kl_u
        if (out_size > Bb) out[Bb] = kl;
    }
}

// ------------------------------------------- launcher
extern "C" void kernel_launch(void* const* d_in, const int* in_sizes, int n_in,
                              void* d_out, int out_size) {
    const float* user_emb = (const float*)d_in[0];
    const float* item_emb = (const float*)d_in[1];
    const float* Wq       = (const float*)d_in[2];
    const float* Wk       = (const float*)d_in[3];
    const float* b_att    = (const float*)d_in[4];
    const float* v_att    = (const float*)d_in[5];
    const float* ln_u_g   = (const float*)d_in[6];
    const float* ln_u_b   = (const float*)d_in[7];
    const float* ln_i_g   = (const float*)d_in[8];
    const float* ln_i_b   = (const float*)d_in[9];
    const float* pred_W   = (const float*)d_in[10];
    const float* pred_b   = (const float*)d_in[11];
    const int* user_hist  = (const int*)d_in[12];
    const int* user_idx   = (const int*)d_in[13];
    const int* item_idx   = (const int*)d_in[14];
    float* out = (float*)d_out;

    const int kw_smem = (64 * PADW + 128 * PADW) * 4;   // 101376 B
    cudaFuncSetAttribute(kw_kernel, cudaFuncAttributeMaxDynamicSharedMemorySize,
                         kw_smem);

    kw_kernel<<<KW_NBLK, 128, kw_smem>>>(item_emb, Wk);
    fused_kernel<<<Bb, 128>>>(user_emb, item_emb, Wq, b_att, v_att,
                              ln_u_g, ln_u_b, ln_i_g, ln_i_b,
                              pred_W, pred_b, user_hist, user_idx, item_idx, out);
    kl_reduce_kernel<<<1, 256>>>(out, out_size);
}

// round 5
// speedup vs baseline: 1.3882x; 1.0611x over previous
#include <cuda_runtime.h>
#include <cuda_bf16.h>
#include <stdint.h>

#define Dd 128
#define Ll 200
#define Bb 4096
#define NITEMS 100000

// Scratch (static device globals: allocation-free per harness rules)
__device__ __nv_bfloat16 g_KWh[(NITEMS + 1) * Dd];  // item_emb @ Wk (bf16, 25.6MB)
__device__ float g_klp[Bb];
__device__ int   g_cnt[Bb];

// ---------------------------------------------------------------- utilities

__device__ __forceinline__ uint32_t rotl32(uint32_t x, int d) {
    return (x << d) | (x >> (32 - d));
}

// Exact JAX threefry2x32 (20 rounds)
__device__ __forceinline__ void threefry2x32(uint32_t k0, uint32_t k1,
                                             uint32_t c0, uint32_t c1,
                                             uint32_t& o0, uint32_t& o1) {
    uint32_t ks2 = k0 ^ k1 ^ 0x1BD11BDAu;
    uint32_t x0 = c0 + k0, x1 = c1 + k1;
#define TF_R(r) { x0 += x1; x1 = rotl32(x1, r); x1 ^= x0; }
    TF_R(13) TF_R(15) TF_R(26) TF_R(6)  x0 += k1;  x1 += ks2 + 1u;
    TF_R(17) TF_R(29) TF_R(16) TF_R(24) x0 += ks2; x1 += k0 + 2u;
    TF_R(13) TF_R(15) TF_R(26) TF_R(6)  x0 += k0;  x1 += k1 + 3u;
    TF_R(17) TF_R(29) TF_R(16) TF_R(24) x0 += k1;  x1 += ks2 + 4u;
    TF_R(13) TF_R(15) TF_R(26) TF_R(6)  x0 += ks2; x1 += k0 + 5u;
#undef TF_R
    o0 = x0; o1 = x1;
}

// jax.random.normal under jax_threefry_partitionable=True:
//   counter = 64-bit flat index -> (c0 = 0, c1 = idx); 32-bit draw = o0 ^ o1
__device__ __forceinline__ float jax_normal(uint32_t k1, uint32_t idx) {
    uint32_t o0, o1;
    threefry2x32(0u, k1, 0u, idx, o0, o1);
    uint32_t bits = o0 ^ o1;
    float f = __uint_as_float((bits >> 9) | 0x3F800000u) - 1.0f;  // [0,1)
    const float LO = -0.99999994f;                                // nextafter(-1,0)
    float u = fmaf(f, 2.0f, LO);
    u = fmaxf(u, LO);
    return 1.41421356f * erfinvf(u);
}

// Single-MUFU tanh
__device__ __forceinline__ float fast_tanh(float x) {
    float y;
    asm("tanh.approx.f32 %0, %1;" : "=f"(y) : "f"(x));
    return y;
}

__device__ __forceinline__ float breduce_sum(float v, volatile float* red) {
    int tid = threadIdx.x, lane = tid & 31, wrp = tid >> 5;
#pragma unroll
    for (int o = 16; o; o >>= 1) v += __shfl_down_sync(0xffffffffu, v, o);
    if (lane == 0) red[wrp] = v;
    __syncthreads();
    float r = (red[0] + red[1]) + (red[2] + red[3]);
    __syncthreads();
    return r;
}

__device__ __forceinline__ float breduce_max(float v, volatile float* red) {
    int tid = threadIdx.x, lane = tid & 31, wrp = tid >> 5;
#pragma unroll
    for (int o = 16; o; o >>= 1) v = fmaxf(v, __shfl_down_sync(0xffffffffu, v, o));
    if (lane == 0) red[wrp] = v;
    __syncthreads();
    float r = fmaxf(fmaxf(red[0], red[1]), fmaxf(red[2], red[3]));
    __syncthreads();
    return r;
}

// ------------------------------------------- Kernel A: KW = item_emb @ Wk
// tf32 tensor-core GEMM, persistent 148 blocks x 256 threads.
// 128-row A tiles, double-buffered via cp.async. Wk^T resident in shared.
// Warp grid 4x2: warp covers 32 rows x 64 cols (2 m16 x 8 n8), 16 k-steps.
// Output stored bf16.
#define KW_GRID 148
#define KW_TILES ((NITEMS + 1 + 127) / 128)   // 782
#define PADW 132

__global__ __launch_bounds__(256) void kw_kernel(const float* __restrict__ item_emb,
                                                 const float* __restrict__ Wk) {
    extern __shared__ float smem_f[];
    float* sW  = smem_f;                  // [128 n][132 k]  (transposed Wk)
    float* sA0 = smem_f + 128 * PADW;
    float* sA1 = sA0 + 128 * PADW;

    const int tid  = threadIdx.x;
    const int lane = tid & 31;
    const int wid  = tid >> 5;
    const int gid  = lane >> 2;      // 0..7
    const int tig  = lane & 3;       // 0..3
    const int stripe = (wid & 3) * 32;
    const int colh   = (wid >> 2) * 64;

    // Wk transposed into shared (raw fp32; MMA truncates to tf32 in HW)
    for (int i = tid; i < 128 * 128; i += 256) {
        int k = i >> 7, n = i & 127;
        sW[n * PADW + k] = Wk[k * Dd + n];
    }

    float* bufs[2] = { sA0, sA1 };
    int cur = 0;
    int t = blockIdx.x;

    // async tile loader: 128 rows x 32 16B-chunks
#define LOAD_TILE(dst, tt) do {                                               \
        const int row0_ = (tt) * 128;                                         \
        for (int i = tid; i < 128 * 32; i += 256) {                           \
            int r_ = i >> 5, c_ = i & 31;                                     \
            int sr_ = row0_ + r_; if (sr_ > NITEMS) sr_ = NITEMS;             \
            const float* src_ = item_emb + (size_t)sr_ * Dd + c_ * 4;         \
            uint32_t d_ = (uint32_t)__cvta_generic_to_shared(                 \
                              (dst) + r_ * PADW + c_ * 4);                    \
            asm volatile("cp.async.ca.shared.global [%0], [%1], 16;\n"        \
                         :: "r"(d_), "l"(src_));                              \
        }                                                                     \
    } while (0)

    if (t < KW_TILES) LOAD_TILE(bufs[0], t);
    asm volatile("cp.async.commit_group;\n");

    while (t < KW_TILES) {
        int tn = t + KW_GRID;
        if (tn < KW_TILES) LOAD_TILE(bufs[cur ^ 1], tn);
        asm volatile("cp.async.commit_group;\n");
        asm volatile("cp.async.wait_group 1;\n");
        __syncthreads();

        float* sA = bufs[cur];
        float acc[2][8][4];
#pragma unroll
        for (int mi = 0; mi < 2; mi++)
#pragma unroll
            for (int ni = 0; ni < 8; ni++)
#pragma unroll
                for (int j = 0; j < 4; j++) acc[mi][ni][j] = 0.f;

#pragma unroll
        for (int ks = 0; ks < 16; ks++) {
            const int k0 = ks * 8;
            uint32_t a[2][4];
#pragma unroll
            for (int mi = 0; mi < 2; mi++) {
                int r = stripe + mi * 16 + gid;
                a[mi][0] = __float_as_uint(sA[r * PADW + k0 + tig]);
                a[mi][1] = __float_as_uint(sA[(r + 8) * PADW + k0 + tig]);
                a[mi][2] = __float_as_uint(sA[r * PADW + k0 + tig + 4]);
                a[mi][3] = __float_as_uint(sA[(r + 8) * PADW + k0 + tig + 4]);
            }
            uint32_t bfr[8][2];
#pragma unroll
            for (int ni = 0; ni < 8; ni++) {
                int n = colh + ni * 8 + gid;
                bfr[ni][0] = __float_as_uint(sW[n * PADW + k0 + tig]);
                bfr[ni][1] = __float_as_uint(sW[n * PADW + k0 + tig + 4]);
            }
#pragma unroll
            for (int mi = 0; mi < 2; mi++)
#pragma unroll
                for (int ni = 0; ni < 8; ni++) {
                    asm volatile(
                        "mma.sync.aligned.m16n8k8.row.col.f32.tf32.tf32.f32 "
                        "{%0,%1,%2,%3}, {%4,%5,%6,%7}, {%8,%9}, {%0,%1,%2,%3};"
                        : "+f"(acc[mi][ni][0]), "+f"(acc[mi][ni][1]),
                          "+f"(acc[mi][ni][2]), "+f"(acc[mi][ni][3])
                        : "r"(a[mi][0]), "r"(a[mi][1]), "r"(a[mi][2]), "r"(a[mi][3]),
                          "r"(bfr[ni][0]), "r"(bfr[ni][1]));
                }
        }

        // epilogue: bf16 pack + store
        const int row0 = t * 128;
        uint32_t* kw32 = (uint32_t*)g_KWh;
#pragma unroll
        for (int mi = 0; mi < 2; mi++) {
            int r0 = row0 + stripe + mi * 16 + gid;
            int r1 = r0 + 8;
#pragma unroll
            for (int ni = 0; ni < 8; ni++) {
                int c = colh + ni * 8 + tig * 2;
                if (r0 <= NITEMS) {
                    __nv_bfloat162 h = __floats2bfloat162_rn(acc[mi][ni][0], acc[mi][ni][1]);
                    kw32[(size_t)r0 * (Dd / 2) + (c >> 1)] = *(uint32_t*)&h;
                }
                if (r1 <= NITEMS) {
                    __nv_bfloat162 h = __floats2bfloat162_rn(acc[mi][ni][2], acc[mi][ni][3]);
                    kw32[(size_t)r1 * (Dd / 2) + (c >> 1)] = *(uint32_t*)&h;
                }
            }
        }
        __syncthreads();
        cur ^= 1;
        t = tn;
    }
#undef LOAD_TILE
}

// ------------------------------------------- Kernel C: fused BAM forward
__global__ __launch_bounds__(128) void fused_kernel(
    const float* __restrict__ user_emb,
    const float* __restrict__ item_emb,
    const float* __restrict__ Wq,
    const float* __restrict__ b_att,
    const float* __restrict__ v_att,
    const float* __restrict__ ln_u_g, const float* __restrict__ ln_u_b,
    const float* __restrict__ ln_i_g, const float* __restrict__ ln_i_b,
    const float* __restrict__ pred_W, const float* __restrict__ pred_b,
    const int* __restrict__ user_hist,
    const int* __restrict__ user_idx,
    const int* __restrict__ item_idx,
    float* __restrict__ out)
{
    __shared__ __align__(16) float sh_q[Dd];
    __shared__ __align__(16) float sh_u[Dd];
    __shared__ __align__(16) float sh_v[Dd];
    __shared__ int   sh_r[Ll];
    __shared__ float sh_s[Ll];
    __shared__ float sh_w1[Ll];
    __shared__ float sh_w2[Ll];
    __shared__ float red[4];

    const int tid  = threadIdx.x;
    const int lane = tid & 31;
    const int wrp  = tid >> 5;
    const int b    = blockIdx.x;
    const int uidx = user_idx[b];
    const int tgt  = item_idx[b];

    sh_u[tid] = user_emb[(size_t)uidx * Dd + tid];
    sh_v[tid] = v_att[tid];
    float validf = 0.f;
    for (int l = tid; l < Ll; l += 128) {
        int r = user_hist[(size_t)uidx * Ll + l];
        bool ok = (r != tgt) && (r != NITEMS);
        sh_r[l] = ok ? r : -1;
        validf += ok ? 1.f : 0.f;
    }
    __syncthreads();

    // qq = user_row @ Wq + b_att  (thread owns output column tid)
    float acc = b_att[tid];
#pragma unroll 8
    for (int e = 0; e < Dd; e++)
        acc = fmaf(sh_u[e], Wq[e * Dd + tid], acc);
    sh_q[tid] = acc;

    float nvf = breduce_sum(validf, red);   // also syncs sh_q
    int n_valid = (int)(nvf + 0.5f);
    float nv_clamped = (n_valid > 0) ? (float)n_valid : 1.0f;
    float mu_p = -logf(nv_clamped);

    // scores: warp per l, 2 rows per iteration for MLP; lane covers 4 dims (8B bf16)
    float4 q4, v4;
    {
        float2 qa = *(const float2*)(sh_q + lane * 4);
        float2 qb = *(const float2*)(sh_q + lane * 4 + 2);
        q4 = make_float4(qa.x, qa.y, qb.x, qb.y);
        float2 va = *(const float2*)(sh_v + lane * 4);
        float2 vb = *(const float2*)(sh_v + lane * 4 + 2);
        v4 = make_float4(va.x, va.y, vb.x, vb.y);
    }
    for (int l = wrp; l < Ll; l += 8) {
        int l1 = l + 4;
        int r0 = sh_r[l];
        int r1 = (l1 < Ll) ? sh_r[l1] : -1;
        uint2 raw0 = make_uint2(0u, 0u), raw1 = make_uint2(0u, 0u);
        if (r0 >= 0)
            raw0 = ((const uint2*)(g_KWh + (size_t)r0 * Dd))[lane];
        if (r1 >= 0)
            raw1 = ((const uint2*)(g_KWh + (size_t)r1 * Dd))[lane];

#pragma unroll
        for (int j = 0; j < 2; j++) {
            int rr = j ? r1 : r0;
            int ll = j ? l1 : l;
            if (ll >= Ll) break;
            float sval = -1e30f;
            if (rr >= 0) {
                uint2 raw = j ? raw1 : raw0;
                float2 f0 = __bfloat1622float2(*(__nv_bfloat162*)&raw.x);
                float2 f1 = __bfloat1622float2(*(__nv_bfloat162*)&raw.y);
                float tv = v4.x * fast_tanh(q4.x + f0.x);
                tv = fmaf(v4.y, fast_tanh(q4.y + f0.y), tv);
                tv = fmaf(v4.z, fast_tanh(q4.z + f1.x), tv);
                tv = fmaf(v4.w, fast_tanh(q4.w + f1.y), tv);
#pragma unroll
                for (int o = 16; o; o >>= 1)
                    tv += __shfl_down_sync(0xffffffffu, tv, o);
                sval = tv * 0.25f;   // / TAU
            }
            if (lane == 0) sh_s[ll] = sval;
        }
    }
    __syncthreads();

    // softmax
    float m = -1e30f;
    for (int l = tid; l < Ll; l += 128) m = fmaxf(m, sh_s[l]);
    m = breduce_max(m, red);

    float esum = 0.f;
    for (int l = tid; l < Ll; l += 128) {
        float e = 0.f;
        if (sh_r[l] >= 0) e = expf(sh_s[l] - m);
        sh_s[l] = e;
        esum += e;
    }
    esum = breduce_sum(esum, red);
    float inv_es = (esum > 0.f) ? (1.0f / esum) : 0.f;

    // lognormal sampling (exact JAX partitionable threefry) + KL
    float klacc = 0.f;
    for (int l = tid; l < Ll; l += 128) {
        float w1 = 0.f, w2 = 0.f;
        if (sh_r[l] >= 0) {
            float alpha = sh_s[l] * inv_es;
            float mu = logf(alpha + 1e-24f);
            uint32_t idx = (uint32_t)(b * Ll + l);
            float e1 = jax_normal(1u, idx);
            float e2 = jax_normal(2u, idx);
            w1 = expf(fmaf(0.1f, e1, mu));
            w2 = expf(fmaf(0.1f, e2, mu));
            float dmu = mu - mu_p;
            klacc += 1.8075851f + 0.5f * dmu * dmu;  // log(10)-0.5+SIG_Q^2/2 + d^2/2
        }
        sh_w1[l] = w1;
        sh_w2[l] = w2;
    }
    float klsum = breduce_sum(klacc, red);
    if (tid == 0) { g_klp[b] = klsum; g_cnt[b] = n_valid; }

    float s1 = 0.f, s2 = 0.f;
    for (int l = tid; l < Ll; l += 128) { s1 += sh_w1[l]; s2 += sh_w2[l]; }
    float S1 = breduce_sum(s1, red);
    float S2 = breduce_sum(s2, red);
    float i1 = 1.0f / (S1 + 1e-12f);
    float i2 = 1.0f / (S2 + 1e-12f);

    // contexts: 4 batched loads per group (single gather serves both draws)
    float cu = 0.f, ci = 0.f;
    for (int l0 = 0; l0 < Ll; l0 += 4) {
        float vv[4];
#pragma unroll
        for (int j = 0; j < 4; j++) {
            int r = sh_r[l0 + j];
            vv[j] = (r >= 0) ? item_emb[(size_t)r * Dd + tid] : 0.f;
        }
#pragma unroll
        for (int j = 0; j < 4; j++) {
            cu = fmaf(sh_w1[l0 + j], vv[j], cu);
            ci = fmaf(sh_w2[l0 + j], vv[j], ci);
        }
    }
    cu *= i1; ci *= i2;

    // layernorm(u ctx * user_emb)
    float xu = cu * sh_u[tid];
    float mean_u = breduce_sum(xu, red) * (1.0f / Dd);
    float du = xu - mean_u;
    float var_u = breduce_sum(du * du, red) * (1.0f / Dd);
    float us = du * rsqrtf(var_u + 1e-5f) * ln_u_g[tid] + ln_u_b[tid];

    // layernorm(i ctx * item_emb[target])
    float xi = ci * item_emb[(size_t)tgt * Dd + tid];
    float mean_i = breduce_sum(xi, red) * (1.0f / Dd);
    float di = xi - mean_i;
    float var_i = breduce_sum(di * di, red) * (1.0f / Dd);
    float is_ = di * rsqrtf(var_i + 1e-5f) * ln_i_g[tid] + ln_i_b[tid];

    float pv = us * is_ * pred_W[tid];
    float dot = breduce_sum(pv, red);
    if (tid == 0) out[b] = dot + pred_b[0];
}

// ------------------------------------------- Kernel D: deterministic KL reduce
__global__ __launch_bounds__(256) void kl_reduce_kernel(float* __restrict__ out,
                                                        int out_size) {
    __shared__ float rs[8];
    __shared__ int   ri[8];
    int tid = threadIdx.x;
    float s = 0.f; int c = 0;
    for (int i = tid; i < Bb; i += 256) { s += g_klp[i]; c += g_cnt[i]; }
#pragma unroll
    for (int o = 16; o; o >>= 1) {
        s += __shfl_down_sync(0xffffffffu, s, o);
        c += __shfl_down_sync(0xffffffffu, c, o);
    }
    if ((tid & 31) == 0) { rs[tid >> 5] = s; ri[tid >> 5] = c; }
    __syncthreads();
    if (tid == 0) {
        float S = 0.f; int C = 0;
        for (int i = 0; i < 8; i++) { S += rs[i]; C += ri[i]; }
        if (C < 1) C = 1;
        float kl = 0.25f * S / (float)C;   // BETA * sum / cnt ; (kl_u+kl_i)/2 == kl_u
        if (out_size > Bb) out[Bb] = kl;
    }
}

// ------------------------------------------- launcher
extern "C" void kernel_launch(void* const* d_in, const int* in_sizes, int n_in,
                              void* d_out, int out_size) {
    const float* user_emb = (const float*)d_in[0];
    const float* item_emb = (const float*)d_in[1];
    const float* Wq       = (const float*)d_in[2];
    const float* Wk       = (const float*)d_in[3];
    const float* b_att    = (const float*)d_in[4];
    const float* v_att    = (const float*)d_in[5];
    const float* ln_u_g   = (const float*)d_in[6];
    const float* ln_u_b   = (const float*)d_in[7];
    const float* ln_i_g   = (const float*)d_in[8];
    const float* ln_i_b   = (const float*)d_in[9];
    const float* pred_W   = (const float*)d_in[10];
    const float* pred_b   = (const float*)d_in[11];
    const int* user_hist  = (const int*)d_in[12];
    const int* user_idx   = (const int*)d_in[13];
    const int* item_idx   = (const int*)d_in[14];
    float* out = (float*)d_out;

    const int kw_smem = (128 + 2 * 128) * PADW * 4;   // 202752 B
    cudaFuncSetAttribute(kw_kernel, cudaFuncAttributeMaxDynamicSharedMemorySize,
                         kw_smem);

    kw_kernel<<<KW_GRID, 256, kw_smem>>>(item_emb, Wk);
    fused_kernel<<<Bb, 128>>>(user_emb, item_emb, Wq, b_att, v_att,
                              ln_u_g, ln_u_b, ln_i_g, ln_i_b,
                              pred_W, pred_b, user_hist, user_idx, item_idx, out);
    kl_reduce_kernel<<<1, 256>>>(out, out_size);
}